// round 1
// baseline (speedup 1.0000x reference)
#include <cuda_runtime.h>
#include <math.h>
#include <float.h>

#define NB    2048
#define CDIM  512
#define TDIM  1024
#define NBATCH 32
#define NT    (NBATCH * TDIM)      // 32768
#define MUF   0.99f
#define OMMUF (1.0f - MUF)

// Output layout (flattened reference tuple):
//   x_d_out      [32,512,1024] -> 16777216 floats at 0
//   commit_loss  scalar        -> offset 16777216
//   perplexity   scalar        -> offset 16777217
//   new_codebook [2048,512]    -> offset 16777218
//   code_sum_ema [2048,512]    -> offset 17825794
//   code_count_ema [2048]      -> offset 18874370
#define OFF_XD    0
#define OFF_LOSS  16777216
#define OFF_PERP  16777217
#define OFF_NCB   16777218
#define OFF_SEMA  17825794
#define OFF_CEMA  18874370

// ---- scratch (device globals: no runtime allocation) ----
__device__ float  g_cnorm[NB];
__device__ int    g_idx[NT];
__device__ float  g_new_sum[NB * CDIM];
__device__ float  g_new_cnt[NB];
__device__ double g_loss;

// ---------------------------------------------------------------------------
// 1) zero scratch
// ---------------------------------------------------------------------------
__global__ void k_zero() {
    int id = blockIdx.x * blockDim.x + threadIdx.x;
    if (id < NB * CDIM) g_new_sum[id] = 0.0f;
    if (id < NB)        g_new_cnt[id] = 0.0f;
    if (id == 0)        g_loss = 0.0;
}

// ---------------------------------------------------------------------------
// 2) codebook row norms ||c||^2  (one warp per code)
// ---------------------------------------------------------------------------
__global__ void k_cnorm(const float* __restrict__ cb) {
    int w    = (blockIdx.x * blockDim.x + threadIdx.x) >> 5;
    int lane = threadIdx.x & 31;
    if (w >= NB) return;
    const float* row = cb + (size_t)w * CDIM;
    float acc = 0.0f;
    #pragma unroll 4
    for (int k = lane; k < CDIM; k += 32) { float v = row[k]; acc += v * v; }
    #pragma unroll
    for (int m = 16; m; m >>= 1) acc += __shfl_xor_sync(0xffffffffu, acc, m);
    if (lane == 0) g_cnorm[w] = acc;
}

// ---------------------------------------------------------------------------
// 3) fused distance-GEMM + argmin.
//    Block tile: 128 tokens x 128 codes, K chunks of 16.
//    x layout is (N,C,T): A[m][k] = x[n, k, t0+m]  -> contiguous across m.
//    score = ||c||^2 - 2 x.c   (||x||^2 dropped: constant per token)
// ---------------------------------------------------------------------------
#define BM 128
#define BN 128
#define BK 16

__global__ __launch_bounds__(256) void k_argmin(const float* __restrict__ x,
                                                const float* __restrict__ cb) {
    __shared__ float As[BK][BM];
    __shared__ float Bs[BK][BN];
    const int tid = threadIdx.x;
    const int bid = blockIdx.x;            // 0..255; 128 | 1024 so tile stays in one n
    const int n   = bid >> 3;
    const int tl0 = (bid & 7) * BM;
    const float* xb = x + (size_t)n * CDIM * TDIM + tl0;
    const int tx = tid & 15, ty = tid >> 4;

    float runv[8]; int runi[8];
    #pragma unroll
    for (int i = 0; i < 8; i++) { runv[i] = FLT_MAX; runi[i] = 0x7fffffff; }

    for (int ct = 0; ct < NB / BN; ct++) {
        const int c0 = ct * BN;
        float acc[8][8];
        #pragma unroll
        for (int i = 0; i < 8; i++)
            #pragma unroll
            for (int j = 0; j < 8; j++) acc[i][j] = 0.0f;

        for (int kc = 0; kc < CDIM / BK; kc++) {
            const int k0 = kc * BK;
            // A: 16x128 tile, contiguous 128-float rows, float4 loads
            #pragma unroll
            for (int p = 0; p < 2; p++) {
                int q  = tid + p * 256;
                int kk = q >> 5, m4 = (q & 31) << 2;
                float4 v = *reinterpret_cast<const float4*>(xb + (size_t)(k0 + kk) * TDIM + m4);
                *reinterpret_cast<float4*>(&As[kk][m4]) = v;
            }
            // B: codebook rows are K-contiguous; transpose into [k][code]
            #pragma unroll
            for (int p = 0; p < 2; p++) {
                int q  = tid + p * 256;
                int j  = q >> 2, kq = (q & 3) << 2;
                float4 v = *reinterpret_cast<const float4*>(cb + (size_t)(c0 + j) * CDIM + k0 + kq);
                Bs[kq + 0][j] = v.x; Bs[kq + 1][j] = v.y;
                Bs[kq + 2][j] = v.z; Bs[kq + 3][j] = v.w;
            }
            __syncthreads();
            #pragma unroll
            for (int kk = 0; kk < BK; kk++) {
                float a[8], b[8];
                *(float4*)&a[0] = *(const float4*)&As[kk][ty * 8];
                *(float4*)&a[4] = *(const float4*)&As[kk][ty * 8 + 4];
                *(float4*)&b[0] = *(const float4*)&Bs[kk][tx * 8];
                *(float4*)&b[4] = *(const float4*)&Bs[kk][tx * 8 + 4];
                #pragma unroll
                for (int i = 0; i < 8; i++)
                    #pragma unroll
                    for (int j = 0; j < 8; j++) acc[i][j] += a[i] * b[j];
            }
            __syncthreads();
        }

        // epilogue: per-token min over this code tile, then across tx lanes
        float cn[8];
        #pragma unroll
        for (int j = 0; j < 8; j++) cn[j] = g_cnorm[c0 + tx * 8 + j];
        #pragma unroll
        for (int i = 0; i < 8; i++) {
            float bv = FLT_MAX; int bi = 0x7fffffff;
            #pragma unroll
            for (int j = 0; j < 8; j++) {
                float s = cn[j] - 2.0f * acc[i][j];
                if (s < bv) { bv = s; bi = c0 + tx * 8 + j; }   // ascending j: first-min kept
            }
            // butterfly across the 16 tx lanes (lanes 0-15 / 16-31 share ty)
            #pragma unroll
            for (int m = 1; m < 16; m <<= 1) {
                float ov = __shfl_xor_sync(0xffffffffu, bv, m);
                int   oi = __shfl_xor_sync(0xffffffffu, bi, m);
                if (ov < bv || (ov == bv && oi < bi)) { bv = ov; bi = oi; }
            }
            if (bv < runv[i] || (bv == runv[i] && bi < runi[i])) { runv[i] = bv; runi[i] = bi; }
        }
    }
    if (tx == 0) {
        #pragma unroll
        for (int i = 0; i < 8; i++) g_idx[bid * BM + ty * 8 + i] = runi[i];
    }
}

// ---------------------------------------------------------------------------
// 4) gather codebook[idx] -> x_d_out (coalesced over t), segment-sum scatter,
//    commit-loss accumulation. Block = 128 tokens x 2 c-lanes.
// ---------------------------------------------------------------------------
__global__ __launch_bounds__(256) void k_scatter(const float* __restrict__ x,
                                                 const float* __restrict__ cb,
                                                 float* __restrict__ out) {
    const int bid = blockIdx.x;
    const int t0  = bid * 128;
    const int n   = t0 >> 10, tl0 = t0 & 1023;
    __shared__ int sidx[128];
    const int tid = threadIdx.x;
    if (tid < 128) sidx[tid] = g_idx[t0 + tid];
    __syncthreads();
    const int m = tid & 127, ch = tid >> 7;
    const int code = sidx[m];
    const float* xb  = x   + (size_t)n * CDIM * TDIM + tl0 + m;
    float*       ob  = out + OFF_XD + (size_t)n * CDIM * TDIM + tl0 + m;
    const float* cbr = cb + (size_t)code * CDIM;
    float*       gs  = g_new_sum + (size_t)code * CDIM;

    float lacc = 0.0f;
    for (int c = ch; c < CDIM; c += 2) {
        float cv = __ldg(&cbr[c]);
        float xv = xb[(size_t)c * TDIM];
        ob[(size_t)c * TDIM] = cv;
        float d = xv - cv; lacc += d * d;
        atomicAdd(&gs[c], xv);
    }
    if (ch == 0) atomicAdd(&g_new_cnt[code], 1.0f);

    #pragma unroll
    for (int s = 16; s; s >>= 1) lacc += __shfl_xor_sync(0xffffffffu, lacc, s);
    __shared__ float wred[8];
    const int w = tid >> 5, lane = tid & 31;
    if (lane == 0) wred[w] = lacc;
    __syncthreads();
    if (tid == 0) {
        float bs = 0.0f;
        #pragma unroll
        for (int i = 0; i < 8; i++) bs += wred[i];
        atomicAdd(&g_loss, (double)bs);
    }
}

// ---------------------------------------------------------------------------
// 5) EMA + codebook reset update
// ---------------------------------------------------------------------------
__global__ void k_ema(const float* __restrict__ x,
                      const float* __restrict__ code_sum,
                      const float* __restrict__ code_count,
                      float* __restrict__ out) {
    const int id = blockIdx.x * blockDim.x + threadIdx.x;   // 0..NB*CDIM-1
    const int code = id >> 9, c = id & 511;
    const float sema = MUF * code_sum[id]    + OMMUF * g_new_sum[id];
    const float cema = MUF * code_count[code] + OMMUF * g_new_cnt[code];
    out[OFF_SEMA + id] = sema;
    if (c == 0) out[OFF_CEMA + code] = cema;
    const float upd = sema / fmaxf(cema, 1e-10f);
    // out_random = x_flat[code] : row code -> (n = code/T, t = code%T)
    const int nn = code >> 10, tt = code & 1023;
    const float rnd = x[(size_t)nn * CDIM * TDIM + (size_t)c * TDIM + tt];
    out[OFF_NCB + id] = (cema >= 1.0f) ? upd : rnd;
}

// ---------------------------------------------------------------------------
// 6) perplexity + commit loss scalars (single block, 1024 threads)
// ---------------------------------------------------------------------------
__global__ void k_final(float* __restrict__ out) {
    __shared__ float red[32];
    __shared__ float s_total;
    const int tid = threadIdx.x;
    const float c1 = g_new_cnt[tid];
    const float c2 = g_new_cnt[tid + 1024];
    float s = c1 + c2;
    #pragma unroll
    for (int m = 16; m; m >>= 1) s += __shfl_xor_sync(0xffffffffu, s, m);
    const int w = tid >> 5, lane = tid & 31;
    if (lane == 0) red[w] = s;
    __syncthreads();
    if (tid < 32) {
        float v = red[tid];
        #pragma unroll
        for (int m = 16; m; m >>= 1) v += __shfl_xor_sync(0xffffffffu, v, m);
        if (tid == 0) s_total = v;
    }
    __syncthreads();
    const float inv = s_total + 1e-10f;
    const float p1 = c1 / inv, p2 = c2 / inv;
    float e = p1 * logf(p1 + 1e-7f) + p2 * logf(p2 + 1e-7f);
    __syncthreads();
    #pragma unroll
    for (int m = 16; m; m >>= 1) e += __shfl_xor_sync(0xffffffffu, e, m);
    if (lane == 0) red[w] = e;
    __syncthreads();
    if (tid < 32) {
        float v = red[tid];
        #pragma unroll
        for (int m = 16; m; m >>= 1) v += __shfl_xor_sync(0xffffffffu, v, m);
        if (tid == 0) {
            out[OFF_PERP] = expf(-v);
            out[OFF_LOSS] = (float)(g_loss / (double)((size_t)NT * CDIM));
        }
    }
}

// ---------------------------------------------------------------------------
extern "C" void kernel_launch(void* const* d_in, const int* in_sizes, int n_in,
                              void* d_out, int out_size) {
    const float* x    = (const float*)d_in[0];
    const float* cb   = (const float*)d_in[1];
    const float* csum = (const float*)d_in[2];
    const float* ccnt = (const float*)d_in[3];
    float* out = (float*)d_out;

    k_zero   <<<(NB * CDIM + 255) / 256, 256>>>();
    k_cnorm  <<<NB / 8, 256>>>(cb);
    k_argmin <<<NT / BM, 256>>>(x, cb);
    k_scatter<<<NT / 128, 256>>>(x, cb, out);
    k_ema    <<<(NB * CDIM) / 256, 256>>>(x, csum, ccnt, out);
    k_final  <<<1, 1024>>>(out);
}

// round 11
// speedup vs baseline: 1.4206x; 1.4206x over previous
#include <cuda_runtime.h>
#include <cuda_bf16.h>
#include <math.h>
#include <float.h>
#include <stdint.h>

#define NB    2048
#define CDIM  512
#define TDIM  1024
#define NT    32768
#define MUF   0.99f
#define OMMUF 0.01f

#define OFF_LOSS  16777216
#define OFF_PERP  16777217
#define OFF_NCB   16777218
#define OFF_SEMA  17825794
#define OFF_CEMA  18874370

#define MTILES  256
#define NTILES  8
#define TAU     0.05f

// GEMM tiling: CTA 128(M) x 256(N) x 32(K-chunk), 48 chunks (3 terms x 512)
#define ASZ   10240                 // 128 rows x 80B (64B data + 16B pad)
#define BSZ   20480                 // 256 rows x 80B
#define STAGE (ASZ + BSZ)           // 30720
#define NSTG  4
#define SM_CN (NSTG * STAGE)
#define SMT   (SM_CN + 1024)        // 123904

// ---- device-global scratch ----
__device__ uint4  g_A[(size_t)MTILES * 2 * 128 * 1024 / 16];   // [mt][plane][row128][k512] bf16
__device__ uint4  g_B[(size_t)2 * NB * 1024 / 16];             // [plane][code][k512] bf16
__device__ float4 g_top2[(size_t)MTILES * NTILES * 4 * 128];   // per (mt,nt,warp_n,row)
__device__ float  g_cnorm[NB];
__device__ int    g_idx[NT];
__device__ float  g_new_sum[NB * CDIM];
__device__ float  g_new_cnt[NB];
__device__ double g_loss;

// ---------------- helpers ----------------
__device__ __forceinline__ uint32_t smem_u32(const void* p) {
    uint32_t a;
    asm("{ .reg .u64 t; cvta.to.shared.u64 t, %1; cvt.u32.u64 %0, t; }" : "=r"(a) : "l"(p));
    return a;
}
__device__ __forceinline__ void cpasync16(uint32_t dst, const void* src) {
    asm volatile("cp.async.cg.shared.global [%0], [%1], 16;" :: "r"(dst), "l"(src));
}
__device__ __forceinline__ void mma16816(float* c, const uint32_t* a, const uint32_t* b) {
    asm volatile("mma.sync.aligned.m16n8k16.row.col.f32.bf16.bf16.f32 "
                 "{%0,%1,%2,%3}, {%4,%5,%6,%7}, {%8,%9}, {%0,%1,%2,%3};"
                 : "+f"(c[0]), "+f"(c[1]), "+f"(c[2]), "+f"(c[3])
                 : "r"(a[0]), "r"(a[1]), "r"(a[2]), "r"(a[3]), "r"(b[0]), "r"(b[1]));
}
__device__ __forceinline__ uint32_t pack_hi(float v0, float v1, uint32_t& lo) {
    __nv_bfloat16 h0 = __float2bfloat16(v0), h1 = __float2bfloat16(v1);
    __nv_bfloat16 l0 = __float2bfloat16(v0 - __bfloat162float(h0));
    __nv_bfloat16 l1 = __float2bfloat16(v1 - __bfloat162float(h1));
    lo = (uint32_t)__bfloat16_as_ushort(l0) | ((uint32_t)__bfloat16_as_ushort(l1) << 16);
    return (uint32_t)__bfloat16_as_ushort(h0) | ((uint32_t)__bfloat16_as_ushort(h1) << 16);
}

// ---------------- 0) zero scratch ----------------
__global__ void k_zero() {
    int id = blockIdx.x * blockDim.x + threadIdx.x;
    if (id < NB * CDIM) g_new_sum[id] = 0.0f;
    if (id < NB)        g_new_cnt[id] = 0.0f;
    if (id == 0)        g_loss = 0.0;
}

// ---------------- 1) codebook norms ----------------
__global__ void k_cnorm(const float* __restrict__ cb) {
    int w = (blockIdx.x * blockDim.x + threadIdx.x) >> 5;
    int lane = threadIdx.x & 31;
    if (w >= NB) return;
    const float* row = cb + (size_t)w * CDIM;
    float acc = 0.0f;
    #pragma unroll 4
    for (int k = lane; k < CDIM; k += 32) { float v = row[k]; acc += v * v; }
    #pragma unroll
    for (int m = 16; m; m >>= 1) acc += __shfl_xor_sync(0xffffffffu, acc, m);
    if (lane == 0) g_cnorm[w] = acc;
}

// ---------------- 2) prep A: transpose + bf16 split ----------------
__global__ __launch_bounds__(256) void k_prepA(const float* __restrict__ x) {
    __shared__ float sx[64 * 129];
    const int mt = blockIdx.x, ks = blockIdx.y;
    const int c0 = ks * 64;
    const int n = mt >> 3, tl0 = (mt & 7) * 128;
    const float* xb = x + (size_t)n * CDIM * TDIM + tl0;
    const int tid = threadIdx.x;
    #pragma unroll
    for (int i = 0; i < 32; i++) {
        int e = tid + 256 * i;
        int k = e >> 7, r = e & 127;
        sx[k * 129 + r] = xb[(size_t)(c0 + k) * TDIM + r];
    }
    __syncthreads();
    uint32_t* gw = (uint32_t*)g_A;
    const size_t hiB = ((size_t)(mt * 2 + 0) * 128) * 256;
    const size_t loB = ((size_t)(mt * 2 + 1) * 128) * 256;
    #pragma unroll
    for (int j = 0; j < 16; j++) {
        int q = tid + 256 * j;              // 4096 (row, kpair)
        int row = q >> 5, kp = q & 31;
        uint32_t lw;
        uint32_t hw = pack_hi(sx[(2 * kp) * 129 + row], sx[(2 * kp + 1) * 129 + row], lw);
        size_t w = (size_t)row * 256 + (c0 >> 1) + kp;
        gw[hiB + w] = hw;
        gw[loB + w] = lw;
    }
}

// ---------------- 3) prep B: bf16 split ----------------
__global__ __launch_bounds__(256) void k_prepB(const float* __restrict__ cb) {
    uint32_t* gw = (uint32_t*)g_B;
    #pragma unroll
    for (int it = 0; it < 4; it++) {
        int id = blockIdx.x * 1024 + it * 256 + threadIdx.x;   // 524288
        int code = id >> 8, kp = id & 255;
        float2 v = *(const float2*)(cb + (size_t)code * 512 + 2 * kp);
        uint32_t lw;
        uint32_t hw = pack_hi(v.x, v.y, lw);
        gw[(size_t)code * 256 + kp] = hw;
        gw[(size_t)(2048 + code) * 256 + kp] = lw;
    }
}

// ---------------- 4) bf16 mma.sync GEMM + per-warp top-2 epilogue ----------------
__device__ __forceinline__ void load_stage(uint32_t sb, int mt, int nt, int s, int tid) {
    const int buf = s & 3;
    const int term = s >> 4;
    const int kkb = (s & 15) * 64;           // byte offset within 1024B k-row
    const int pa = (term == 2) ? 1 : 0;      // A: hi,hi,lo
    const int pb = (term == 1) ? 1 : 0;      // B: hi,lo,hi
    {   // A: 512 x 16B chunks
        int row = tid >> 2, cc = tid & 3;
        const char* src = (const char*)g_A + (((size_t)(mt * 2 + pa) * 128 + row) << 10) + kkb + cc * 16;
        cpasync16(sb + buf * STAGE + row * 80 + cc * 16, src);
    }
    #pragma unroll
    for (int j = 0; j < 2; j++) {            // B: 1024 x 16B chunks
        int c = tid + j * 512;
        int row = c >> 2, cc = c & 3;
        const char* src = (const char*)g_B + (((size_t)pb * 2048 + nt * 256 + row) << 10) + kkb + cc * 16;
        cpasync16(sb + buf * STAGE + ASZ + row * 80 + cc * 16, src);
    }
    asm volatile("cp.async.commit_group;");
}

__global__ __launch_bounds__(512, 1) void k_gemm() {
    extern __shared__ char smem[];
    const uint32_t sb = smem_u32(smem);
    const int tid = threadIdx.x;
    const int nt = blockIdx.x, mt = blockIdx.y;
    const int wid = tid >> 5, lane = tid & 31;
    const int warp_m = wid >> 2, warp_n = wid & 3;     // 4x4 warps, each 32(M)x64(N)
    const int g = lane >> 2, q = lane & 3;
    float* cns = (float*)(smem + SM_CN);
    if (tid < 256) cns[tid] = g_cnorm[nt * 256 + tid];

    float acc[2][8][4];
    #pragma unroll
    for (int mb = 0; mb < 2; mb++)
        #pragma unroll
        for (int nb = 0; nb < 8; nb++)
            #pragma unroll
            for (int e = 0; e < 4; e++) acc[mb][nb][e] = 0.0f;

    load_stage(sb, mt, nt, 0, tid);
    load_stage(sb, mt, nt, 1, tid);
    load_stage(sb, mt, nt, 2, tid);

    // Direct-LDS fragment bases (PTX m16n8k16 fragment spec, literal).
    const int a_base = (warp_m * 32 + g) * 80 + 4 * q;
    const int b_base = (warp_n * 64 + g) * 80 + 4 * q;

    for (int s = 0; s < 48; s++) {
        if (s + 3 < 48) load_stage(sb, mt, nt, s + 3, tid);
        if (s <= 44)      asm volatile("cp.async.wait_group 3;");
        else if (s == 45) asm volatile("cp.async.wait_group 2;");
        else if (s == 46) asm volatile("cp.async.wait_group 1;");
        else              asm volatile("cp.async.wait_group 0;");
        __syncthreads();
        const char* Ab = smem + (s & 3) * STAGE;
        const char* Bb = Ab + ASZ;
        #pragma unroll
        for (int kh = 0; kh < 2; kh++) {
            const int kb = kh * 32;
            uint32_t a[2][4], b[8][2];
            #pragma unroll
            for (int mb = 0; mb < 2; mb++) {
                const char* p = Ab + a_base + mb * (16 * 80) + kb;
                a[mb][0] = *(const uint32_t*)(p);
                a[mb][1] = *(const uint32_t*)(p + 8 * 80);
                a[mb][2] = *(const uint32_t*)(p + 16);
                a[mb][3] = *(const uint32_t*)(p + 8 * 80 + 16);
            }
            #pragma unroll
            for (int nb = 0; nb < 8; nb++) {
                const char* p = Bb + b_base + nb * (8 * 80) + kb;
                b[nb][0] = *(const uint32_t*)(p);
                b[nb][1] = *(const uint32_t*)(p + 16);
            }
            #pragma unroll
            for (int mb = 0; mb < 2; mb++)
                #pragma unroll
                for (int nb = 0; nb < 8; nb++)
                    mma16816(acc[mb][nb], a[mb], b[nb]);
        }
        __syncthreads();
    }

    // epilogue: per-warp (64-column) top-2 per token row; each warp_n writes ITS OWN slot.
    #pragma unroll
    for (int mb = 0; mb < 2; mb++) {
        #pragma unroll
        for (int half = 0; half < 2; half++) {
            float v1 = FLT_MAX, v2 = FLT_MAX; int i1 = 0x7fffffff, i2 = 0x7fffffff;
            #pragma unroll
            for (int nb = 0; nb < 8; nb++) {
                #pragma unroll
                for (int e = 0; e < 2; e++) {
                    int col = warp_n * 64 + nb * 8 + q * 2 + e;
                    float sc = cns[col] - 2.0f * acc[mb][nb][half * 2 + e];
                    int ci = nt * 256 + col;
                    if (sc < v1)      { v2 = v1; i2 = i1; v1 = sc; i1 = ci; }
                    else if (sc < v2) { v2 = sc; i2 = ci; }
                }
            }
            #pragma unroll
            for (int off = 1; off <= 2; off <<= 1) {
                float mv1 = __shfl_xor_sync(0xffffffffu, v1, off);
                int   mi1 = __shfl_xor_sync(0xffffffffu, i1, off);
                float mv2 = __shfl_xor_sync(0xffffffffu, v2, off);
                int   mi2 = __shfl_xor_sync(0xffffffffu, i2, off);
                if (mv1 < v1 || (mv1 == v1 && mi1 < i1)) { v2 = v1; i2 = i1; v1 = mv1; i1 = mi1; }
                else if (mv1 < v2 || (mv1 == v2 && mi1 < i2)) { v2 = mv1; i2 = mi1; }
                if (mv2 < v2 || (mv2 == v2 && mi2 < i2)) { v2 = mv2; i2 = mi2; }
            }
            if (q == 0) {
                int row = warp_m * 32 + mb * 16 + half * 8 + g;
                g_top2[(((size_t)mt * NTILES + nt) * 4 + warp_n) * 128 + row] =
                    make_float4(v1, __int_as_float(i1), v2, __int_as_float(i2));
            }
        }
    }
}

// ---------------- 5) merge top-2 (8 nt x 4 warp_n slots) + exact rescue ----------------
__global__ void k_merge(const float* __restrict__ x, const float* __restrict__ cb) {
    const int tk = blockIdx.x * blockDim.x + threadIdx.x;
    if (tk >= NT) return;
    const int mt = tk >> 7, r = tk & 127;
    float v1 = FLT_MAX, v2 = FLT_MAX; int i1 = 0x7fffffff, i2 = 0x7fffffff;
    const float4* base = g_top2 + (size_t)mt * NTILES * 4 * 128 + r;
    #pragma unroll
    for (int s = 0; s < NTILES * 4; s++) {
        float4 e = base[(size_t)s * 128];
        float a = e.x; int ai = __float_as_int(e.y);
        if (a < v1 || (a == v1 && ai < i1)) { v2 = v1; i2 = i1; v1 = a; i1 = ai; }
        else if (a < v2)                    { v2 = a; i2 = ai; }
        a = e.z; ai = __float_as_int(e.w);
        if (a < v1 || (a == v1 && ai < i1)) { v2 = v1; i2 = i1; v1 = a; i1 = ai; }
        else if (a < v2)                    { v2 = a; i2 = ai; }
    }
    int best = i1;
    if (v2 - v1 < TAU) {
        const int n = tk >> 10, t = tk & 1023;
        const float* xc = x + (size_t)n * CDIM * TDIM + t;
        const float* c1 = cb + (size_t)i1 * CDIM;
        const float* c2 = cb + (size_t)i2 * CDIM;
        double s1 = 0.0, s2 = 0.0;
        for (int c = 0; c < CDIM; c++) {
            double xv = (double)xc[(size_t)c * TDIM];
            s1 += xv * (double)c1[c];
            s2 += xv * (double)c2[c];
        }
        double e1 = (double)g_cnorm[i1] - 2.0 * s1;
        double e2 = (double)g_cnorm[i2] - 2.0 * s2;
        if (e2 < e1 || (e2 == e1 && i2 < i1)) best = i2;
    }
    g_idx[tk] = best;
}

// ---------------- 6) gather + segment-sum + loss ----------------
__global__ __launch_bounds__(256) void k_scatter(const float* __restrict__ x,
                                                 const float* __restrict__ cb,
                                                 float* __restrict__ out) {
    const int bid = blockIdx.x;            // 1024 blocks x 32 tokens
    const int t0 = bid * 32;
    const int n = t0 >> 10, tl0 = t0 & 1023;
    __shared__ int sidx[32];
    const int tid = threadIdx.x;
    if (tid < 32) sidx[tid] = g_idx[t0 + tid];
    __syncthreads();
    const int m = tid & 31, ch = tid >> 5;
    const int code = sidx[m];
    const float* xb  = x   + (size_t)n * CDIM * TDIM + tl0 + m;
    float*       ob  = out + (size_t)n * CDIM * TDIM + tl0 + m;
    const float* cbr = cb + (size_t)code * CDIM;
    float*       gs  = g_new_sum + (size_t)code * CDIM;
    float lacc = 0.0f;
    #pragma unroll 4
    for (int c = ch; c < CDIM; c += 8) {
        float cv = __ldg(&cbr[c]);
        float xv = xb[(size_t)c * TDIM];
        ob[(size_t)c * TDIM] = cv;
        float d = xv - cv; lacc += d * d;
        atomicAdd(&gs[c], xv);
    }
    if (ch == 0) atomicAdd(&g_new_cnt[code], 1.0f);
    #pragma unroll
    for (int s = 16; s; s >>= 1) lacc += __shfl_xor_sync(0xffffffffu, lacc, s);
    __shared__ float wred[8];
    const int w = tid >> 5, lane = tid & 31;
    if (lane == 0) wred[w] = lacc;
    __syncthreads();
    if (tid == 0) {
        float bs = 0.0f;
        #pragma unroll
        for (int i = 0; i < 8; i++) bs += wred[i];
        atomicAdd(&g_loss, (double)bs);
    }
}

// ---------------- 7) EMA + reset ----------------
__global__ void k_ema(const float* __restrict__ x,
                      const float* __restrict__ code_sum,
                      const float* __restrict__ code_count,
                      float* __restrict__ out) {
    const int id = blockIdx.x * blockDim.x + threadIdx.x;
    const int code = id >> 9, c = id & 511;
    const float sema = MUF * code_sum[id]     + OMMUF * g_new_sum[id];
    const float cema = MUF * code_count[code] + OMMUF * g_new_cnt[code];
    out[OFF_SEMA + id] = sema;
    if (c == 0) out[OFF_CEMA + code] = cema;
    const float upd = sema / fmaxf(cema, 1e-10f);
    const int nn = code >> 10, tt = code & 1023;
    const float rnd = x[(size_t)nn * CDIM * TDIM + (size_t)c * TDIM + tt];
    out[OFF_NCB + id] = (cema >= 1.0f) ? upd : rnd;
}

// ---------------- 8) scalars ----------------
__global__ void k_final(float* __restrict__ out) {
    __shared__ float red[32];
    __shared__ float s_total;
    const int tid = threadIdx.x;
    const float c1 = g_new_cnt[tid];
    const float c2 = g_new_cnt[tid + 1024];
    float s = c1 + c2;
    #pragma unroll
    for (int m = 16; m; m >>= 1) s += __shfl_xor_sync(0xffffffffu, s, m);
    const int w = tid >> 5, lane = tid & 31;
    if (lane == 0) red[w] = s;
    __syncthreads();
    if (tid < 32) {
        float v = red[tid];
        #pragma unroll
        for (int m = 16; m; m >>= 1) v += __shfl_xor_sync(0xffffffffu, v, m);
        if (tid == 0) s_total = v;
    }
    __syncthreads();
    const float inv = s_total + 1e-10f;
    const float p1 = c1 / inv, p2 = c2 / inv;
    float e = p1 * logf(p1 + 1e-7f) + p2 * logf(p2 + 1e-7f);
    __syncthreads();
    #pragma unroll
    for (int m = 16; m; m >>= 1) e += __shfl_xor_sync(0xffffffffu, e, m);
    if (lane == 0) red[w] = e;
    __syncthreads();
    if (tid < 32) {
        float v = red[tid];
        #pragma unroll
        for (int m = 16; m; m >>= 1) v += __shfl_xor_sync(0xffffffffu, v, m);
        if (tid == 0) {
            out[OFF_PERP] = expf(-v);
            out[OFF_LOSS] = (float)(g_loss / (double)((size_t)NT * CDIM));
        }
    }
}

// ---------------------------------------------------------------------------
extern "C" void kernel_launch(void* const* d_in, const int* in_sizes, int n_in,
                              void* d_out, int out_size) {
    const float* x    = (const float*)d_in[0];
    const float* cb   = (const float*)d_in[1];
    const float* csum = (const float*)d_in[2];
    const float* ccnt = (const float*)d_in[3];
    float* out = (float*)d_out;

    cudaFuncSetAttribute(k_gemm, cudaFuncAttributeMaxDynamicSharedMemorySize, SMT);

    k_zero   <<<(NB * CDIM + 255) / 256, 256>>>();
    k_cnorm  <<<NB / 8, 256>>>(cb);
    k_prepA  <<<dim3(MTILES, 8), 256>>>(x);
    k_prepB  <<<512, 256>>>(cb);
    k_gemm   <<<dim3(NTILES, MTILES), 512, SMT>>>();
    k_merge  <<<NT / 256, 256>>>(x, cb);
    k_scatter<<<NT / 32, 256>>>(x, cb, out);
    k_ema    <<<(NB * CDIM) / 256, 256>>>(x, csum, ccnt, out);
    k_final  <<<1, 1024>>>(out);
}